// round 14
// baseline (speedup 1.0000x reference)
#include <cuda_runtime.h>
#include <cuda_bf16.h>
#include <cstdint>

// Problem constants
#define Bc 2
#define Sc 2048
#define HIDc 2048
#define Hc 16
#define KVc 4
#define Dc 128
#define Gc 4
#define MAXSEQ 4096
#define EPSc 1e-6f
#define NEG_INF (__int_as_float(0xff800000))

typedef __nv_bfloat16 bf16;

// ---------------------------------------------------------------------------
// Helpers (arch-neutral PTX: ldmatrix / mma.sync bf16+tf32 / cp.async)
// ---------------------------------------------------------------------------
__device__ __forceinline__ uint32_t smem_to_u32(const void* p) {
    uint32_t a;
    asm("{ .reg .u64 t; cvta.to.shared.u64 t, %1; cvt.u32.u64 %0, t; }" : "=r"(a) : "l"(p));
    return a;
}
#define SMEM_SWIZZLE_128B(byte_offset) ((byte_offset) ^ (((byte_offset) >> 3) & 0x70))

__device__ __forceinline__ void cp_async16(uint32_t dst, const void* src) {
    asm volatile("cp.async.cg.shared.global [%0], [%1], 16;" :: "r"(dst), "l"(src));
}
#define CP_COMMIT() asm volatile("cp.async.commit_group;" ::: "memory")
#define CP_WAIT2()  asm volatile("cp.async.wait_group 2;" ::: "memory")
#define CP_WAIT1()  asm volatile("cp.async.wait_group 1;" ::: "memory")
#define CP_WAIT0()  asm volatile("cp.async.wait_group 0;" ::: "memory")

__device__ __forceinline__ void ldsm4(uint32_t& r0, uint32_t& r1, uint32_t& r2, uint32_t& r3,
                                      uint32_t addr) {
    asm volatile("ldmatrix.sync.aligned.m8n8.x4.shared.b16 {%0,%1,%2,%3}, [%4];"
                 : "=r"(r0), "=r"(r1), "=r"(r2), "=r"(r3) : "r"(addr));
}
__device__ __forceinline__ void ldsm4t(uint32_t& r0, uint32_t& r1, uint32_t& r2, uint32_t& r3,
                                       uint32_t addr) {
    asm volatile("ldmatrix.sync.aligned.m8n8.x4.trans.shared.b16 {%0,%1,%2,%3}, [%4];"
                 : "=r"(r0), "=r"(r1), "=r"(r2), "=r"(r3) : "r"(addr));
}
__device__ __forceinline__ void mma16816(float* c, const uint32_t* a, const uint32_t* b) {
    asm volatile("mma.sync.aligned.m16n8k16.row.col.f32.bf16.bf16.f32 "
                 "{%0,%1,%2,%3}, {%4,%5,%6,%7}, {%8,%9}, {%0,%1,%2,%3};"
                 : "+f"(c[0]), "+f"(c[1]), "+f"(c[2]), "+f"(c[3])
                 : "r"(a[0]), "r"(a[1]), "r"(a[2]), "r"(a[3]), "r"(b[0]), "r"(b[1]));
}
// tf32 MMA: m16n8k8, A row-major, B col-major
__device__ __forceinline__ void mma1688(float* c, const uint32_t* a, const uint32_t* b) {
    asm volatile("mma.sync.aligned.m16n8k8.row.col.f32.tf32.tf32.f32 "
                 "{%0,%1,%2,%3}, {%4,%5,%6,%7}, {%8,%9}, {%0,%1,%2,%3};"
                 : "+f"(c[0]), "+f"(c[1]), "+f"(c[2]), "+f"(c[3])
                 : "r"(a[0]), "r"(a[1]), "r"(a[2]), "r"(a[3]), "r"(b[0]), "r"(b[1]));
}
__device__ __forceinline__ uint32_t lds32(uint32_t addr) {
    uint32_t v;
    asm volatile("ld.shared.b32 %0, [%1];" : "=r"(v) : "r"(addr));
    return v;
}
__device__ __forceinline__ float ex2(float x) {
    float y;
    asm("ex2.approx.f32 %0, %1;" : "=f"(y) : "f"(x));
    return y;
}
__device__ __forceinline__ float to_tf32(float x) {
    uint32_t u;
    asm("cvt.rna.tf32.f32 %0, %1;" : "=r"(u) : "f"(x));
    return __uint_as_float(u);
}
__device__ __forceinline__ void split_pack(float x, float y, uint32_t& hi, uint32_t& lo) {
    bf16 xh = __float2bfloat16(x);
    bf16 yh = __float2bfloat16(y);
    float xl = x - __bfloat162float(xh);
    float yl = y - __bfloat162float(yh);
    __nv_bfloat162 H; H.x = xh; H.y = yh;
    __nv_bfloat162 L = __floats2bfloat162_rn(xl, yl);
    hi = *(uint32_t*)&H;
    lo = *(uint32_t*)&L;
}
__device__ __forceinline__ void split_pack_p(float x, float y, uint32_t& hi, uint32_t& lo) {
    uint32_t xb = __float_as_uint(x), yb = __float_as_uint(y);
    hi = __byte_perm(xb, yb, 0x7632);
    float xl = x - __uint_as_float(xb & 0xFFFF0000u);
    float yl = y - __uint_as_float(yb & 0xFFFF0000u);
    lo = __byte_perm(__float_as_uint(xl), __float_as_uint(yl), 0x7632);
}

// ---------------------------------------------------------------------------
// Device scratch (fp32 operands for tf32 GEMMs; bf16 splits for flash only)
// ---------------------------------------------------------------------------
__device__ float g_h  [(size_t)4096 * 2048];
__device__ float g_wqt[(size_t)2048 * 2048];
__device__ float g_wkt[(size_t)512 * 2048];
__device__ float g_wvt[(size_t)512 * 2048];
__device__ float g_wot[(size_t)2048 * 2048];
__device__ float g_ctx[(size_t)4096 * 2048];
__device__ float g_q  [(size_t)4096 * 2048];
__device__ bf16 g_khi[(size_t)Bc * Sc * KVc * Dc];
__device__ bf16 g_klo[(size_t)Bc * Sc * KVc * Dc];
__device__ bf16 g_vhi[(size_t)Bc * Sc * KVc * Dc];
__device__ bf16 g_vlo[(size_t)Bc * Sc * KVc * Dc];

// ---------------------------------------------------------------------------
// RMSNorm -> tf32-rounded fp32
// ---------------------------------------------------------------------------
__global__ void __launch_bounds__(256) rmsnorm_kernel(
    const float* __restrict__ x, const float* __restrict__ w, float* __restrict__ h)
{
    int row = blockIdx.x;
    const float* xr = x + (size_t)row * HIDc;
    float ss = 0.f;
    for (int i = threadIdx.x * 4; i < HIDc; i += 1024) {
        float4 t = *(const float4*)(xr + i);
        ss += t.x * t.x + t.y * t.y + t.z * t.z + t.w * t.w;
    }
    #pragma unroll
    for (int o = 16; o > 0; o >>= 1) ss += __shfl_xor_sync(0xffffffffu, ss, o);
    __shared__ float red[8];
    if ((threadIdx.x & 31) == 0) red[threadIdx.x >> 5] = ss;
    __syncthreads();
    float tot = red[0] + red[1] + red[2] + red[3] + red[4] + red[5] + red[6] + red[7];
    float inv = rsqrtf(tot * (1.0f / HIDc) + EPSc);
    float* hr = h + (size_t)row * HIDc;
    for (int i = threadIdx.x * 4; i < HIDc; i += 1024) {
        float4 t = *(const float4*)(xr + i);
        float4 wv = *(const float4*)(w + i);
        float4 o;
        o.x = to_tf32(t.x * inv * wv.x);
        o.y = to_tf32(t.y * inv * wv.y);
        o.z = to_tf32(t.z * inv * wv.z);
        o.w = to_tf32(t.w * inv * wv.w);
        *(float4*)(hr + i) = o;
    }
}

// ---------------------------------------------------------------------------
// Weight transpose: W fp32 [K,N] -> Wt tf32-rounded fp32 [N,K]
// ---------------------------------------------------------------------------
__global__ void __launch_bounds__(256) convert_w_kernel(
    const float* __restrict__ W, float* __restrict__ Wt, int K, int N)
{
    __shared__ float t[32][33];
    int k0 = blockIdx.x * 32;
    int n0 = blockIdx.y * 32;
    int tx = threadIdx.x & 31;
    int ty = threadIdx.x >> 5;
    #pragma unroll
    for (int j = 0; j < 4; j++) {
        int r = ty + 8 * j;
        t[r][tx] = W[(size_t)(k0 + r) * N + n0 + tx];
    }
    __syncthreads();
    #pragma unroll
    for (int j = 0; j < 4; j++) {
        int r = ty + 8 * j;
        Wt[(size_t)(n0 + r) * K + k0 + tx] = to_tf32(t[tx][r]);
    }
}

// ---------------------------------------------------------------------------
// tf32 single-pass GEMM, 128(M)x64(N), BK=64, 2-stage, 2 CTAs/SM.
// A [M,K] fp32 (tf32-rounded), B [N,K] fp32 (tf32-rounded; B col-major view).
// smem: padded pitch 68 floats (272B/row) -> conflict-free scalar frag loads.
// Fused epilogue modes (same as R13):
//   0: C = acc (+res); 1: C = rope(acc+bias) fp32 (also tf32-rounded? no — q stays full fp32);
//   2: rope(acc+bias) -> cache fp32 + split-bf16; 3: (acc+bias) -> cache + split.
// ---------------------------------------------------------------------------
#define PITCHB 272
#define A_TILE_B (128 * PITCHB)     // 34816
#define B_TILE_B (64 * PITCHB)      // 17408
#define G_STAGE  (A_TILE_B + B_TILE_B)  // 52224
#define GM_SMEM_TOTAL (2 * G_STAGE)     // 104448

__global__ void __launch_bounds__(256, 2) gemm_tf32_kernel(
    const float* __restrict__ A, const float* __restrict__ B,
    const float* __restrict__ bias, const float* __restrict__ res,
    float* __restrict__ C, int N, int K,
    int mode,
    const float* __restrict__ cosb, const float* __restrict__ sinb,
    const int* __restrict__ pos,
    float* __restrict__ cacheOut, bf16* __restrict__ shi, bf16* __restrict__ slo)
{
    extern __shared__ char smem[];
    uint32_t sb = smem_to_u32(smem);
    int tid  = threadIdx.x;
    int wid  = tid >> 5;
    int lane = tid & 31;
    int gid  = lane >> 2;      // 0..7
    int tig  = lane & 3;       // 0..3
    int rowBase = blockIdx.y * 128;
    int colBase = blockIdx.x * 64;

    int wm = wid & 3;          // 4 m-warps x 32 rows
    int wn = wid >> 2;         // 2 n-warps x 32 cols
    int wmBase = wm * 32;
    int wnBase = wn * 32;

    const float* gA = A + (size_t)rowBase * K;
    const float* gB = B + (size_t)colBase * K;

    float acc[2][4][4];
    #pragma unroll
    for (int i = 0; i < 2; i++)
        #pragma unroll
        for (int j = 0; j < 4; j++)
            #pragma unroll
            for (int c = 0; c < 4; c++) acc[i][j][c] = 0.f;

    const int KT = K >> 6;

    auto load_stage = [&](int kt, int buf) {
        uint32_t base = sb + buf * G_STAGE;
        int kOff = kt * 64;
        #pragma unroll
        for (int i = 0; i < 8; i++) {       // A: 128 rows x 16 chunks = 2048
            int c = tid + i * 256;
            int row = c >> 4, ch = c & 15;
            cp_async16(base + row * PITCHB + ch * 16, gA + (size_t)row * K + kOff + ch * 4);
        }
        #pragma unroll
        for (int i = 0; i < 4; i++) {       // B: 64 rows x 16 chunks = 1024
            int c = tid + i * 256;
            int row = c >> 4, ch = c & 15;
            cp_async16(base + A_TILE_B + row * PITCHB + ch * 16, gB + (size_t)row * K + kOff + ch * 4);
        }
    };

    load_stage(0, 0);
    CP_COMMIT();

    // fragment base addresses (bytes), advance by 32B per k8 step
    uint32_t aBase[2], bBase[4];
    #pragma unroll
    for (int i = 0; i < 2; i++)
        aBase[i] = (uint32_t)((wmBase + i * 16 + gid) * PITCHB + tig * 4);
    #pragma unroll
    for (int j = 0; j < 4; j++)
        bBase[j] = (uint32_t)(A_TILE_B + (wnBase + j * 8 + gid) * PITCHB + tig * 4);

    for (int kt = 0; kt < KT; kt++) {
        int buf = kt & 1;
        if (kt + 1 < KT) {
            load_stage(kt + 1, buf ^ 1);
            CP_COMMIT();
            CP_WAIT1();
        } else {
            CP_WAIT0();
        }
        __syncthreads();

        uint32_t mb = sb + buf * G_STAGE;
        #pragma unroll
        for (int s = 0; s < 8; s++) {
            uint32_t ko = s * 32;   // 8 floats per step
            uint32_t a[2][4], b[4][2];
            #pragma unroll
            for (int i = 0; i < 2; i++) {
                uint32_t a0 = mb + aBase[i] + ko;
                a[i][0] = lds32(a0);
                a[i][1] = lds32(a0 + 8 * PITCHB);
                a[i][2] = lds32(a0 + 16);
                a[i][3] = lds32(a0 + 8 * PITCHB + 16);
            }
            #pragma unroll
            for (int j = 0; j < 4; j++) {
                uint32_t b0 = mb + bBase[j] + ko;
                b[j][0] = lds32(b0);
                b[j][1] = lds32(b0 + 16);
            }
            #pragma unroll
            for (int i = 0; i < 2; i++)
                #pragma unroll
                for (int j = 0; j < 4; j++) mma1688(acc[i][j], a[i], b[j]);
        }
        __syncthreads();
    }

    // ---- fused epilogue (same modes as R13) ----
    #pragma unroll
    for (int i = 0; i < 2; i++) {
        #pragma unroll
        for (int j = 0; j < 4; j++) {
            int col = colBase + wnBase + j * 8 + tig * 2;   // even
            int r0 = rowBase + wmBase + i * 16 + gid;
            int r1 = r0 + 8;
            float b0 = 0.f, b1 = 0.f;
            if (bias) { b0 = __ldg(bias + col); b1 = __ldg(bias + col + 1); }
            float v0 = acc[i][j][0] + b0, v1 = acc[i][j][1] + b1;
            float v2 = acc[i][j][2] + b0, v3 = acc[i][j][3] + b1;
            if (res) {
                const float* p0 = res + (size_t)r0 * N + col;
                const float* p1 = res + (size_t)r1 * N + col;
                v0 += p0[0]; v1 += p0[1];
                v2 += p1[0]; v3 += p1[1];
            }
            if (mode == 1 || mode == 2) {
                int d = col & (Dc - 1);
                float c0 = __ldg(cosb + (size_t)r0 * Dc + d);
                float s0 = __ldg(sinb + (size_t)r0 * Dc + d);
                float c1 = __ldg(cosb + (size_t)r1 * Dc + d);
                float s1 = __ldg(sinb + (size_t)r1 * Dc + d);
                float t0 = v0 * c0 - v1 * s0; v1 = v1 * c0 + v0 * s0; v0 = t0;
                float t2 = v2 * c1 - v3 * s1; v3 = v3 * c1 + v2 * s1; v2 = t2;
            }
            if (mode <= 1) {
                *(float2*)(C + (size_t)r0 * N + col) = make_float2(v0, v1);
                *(float2*)(C + (size_t)r1 * N + col) = make_float2(v2, v3);
            } else {
                int s0i = r0 & (Sc - 1), bb0 = r0 >> 11;
                int s1i = r1 & (Sc - 1), bb1 = r1 >> 11;
                int p0 = __ldg(pos + s0i);
                int p1 = __ldg(pos + s1i);
                *(float2*)(cacheOut + ((size_t)bb0 * MAXSEQ + p0) * N + col) = make_float2(v0, v1);
                *(float2*)(cacheOut + ((size_t)bb1 * MAXSEQ + p1) * N + col) = make_float2(v2, v3);
                uint32_t hh, ll;
                split_pack(v0, v1, hh, ll);
                *(uint32_t*)(shi + (size_t)r0 * N + col) = hh;
                *(uint32_t*)(slo + (size_t)r0 * N + col) = ll;
                split_pack(v2, v3, hh, ll);
                *(uint32_t*)(shi + (size_t)r1 * N + col) = hh;
                *(uint32_t*)(slo + (size_t)r1 * N + col) = ll;
            }
        }
    }
}

// ---------------------------------------------------------------------------
// Tensor-core flash attention (unchanged math; outputs fp32 ctx tf32-rounded)
// ---------------------------------------------------------------------------
#define FT_STAGE 65536
#define FT_SMEM (3 * FT_STAGE)   // 196608

__global__ void __launch_bounds__(256, 1) flash_mma_kernel(
    const float* __restrict__ q,
    const bf16* __restrict__ khi, const bf16* __restrict__ klo,
    const bf16* __restrict__ vhi, const bf16* __restrict__ vlo,
    float* __restrict__ ctx)
{
    extern __shared__ char smem[];
    uint32_t sb = smem_to_u32(smem);
    int qt = gridDim.x - 1 - blockIdx.x;
    int h = blockIdx.y, b = blockIdx.z;
    int kvh = h >> 2;
    int tid = threadIdx.x, wid = tid >> 5, lane = tid & 31;
    int qbase = qt * 128;
    int r0 = qbase + wid * 16 + (lane >> 2);

    const float scale = 0.08838834764831845f * 1.4426950408889634f;

    uint32_t qa_hi[8][4], qa_lo[8][4];
    {
        const float* q0 = q + (((size_t)b * Sc + r0) * Hc + h) * Dc;
        const float* q1 = q0 + (size_t)8 * Hc * Dc;
        #pragma unroll
        for (int kk = 0; kk < 8; kk++) {
            int c0 = kk * 16 + (lane & 3) * 2;
            split_pack(q0[c0] * scale, q0[c0 + 1] * scale, qa_hi[kk][0], qa_lo[kk][0]);
            split_pack(q1[c0] * scale, q1[c0 + 1] * scale, qa_hi[kk][1], qa_lo[kk][1]);
            split_pack(q0[c0 + 8] * scale, q0[c0 + 9] * scale, qa_hi[kk][2], qa_lo[kk][2]);
            split_pack(q1[c0 + 8] * scale, q1[c0 + 9] * scale, qa_hi[kk][3], qa_lo[kk][3]);
        }
    }

    float oacc[16][4];
    #pragma unroll
    for (int j = 0; j < 16; j++)
        #pragma unroll
        for (int c = 0; c < 4; c++) oacc[j][c] = 0.f;
    float m0 = NEG_INF, m1 = NEG_INF, l0 = 0.f, l1 = 0.f;

    const bf16* mats[4];
    {
        size_t off = (size_t)b * Sc * KVc * Dc + (size_t)kvh * Dc;
        mats[0] = khi + off; mats[1] = klo + off; mats[2] = vhi + off; mats[3] = vlo + off;
    }

    const int NT = 2 * qt + 2;

    auto load_stage = [&](int kt, int buf) {
        int kb = kt * 64;
        #pragma unroll
        for (int i = 0; i < 16; i++) {
            int idx = tid + i * 256;
            int mm = idx >> 10;
            int t  = (idx >> 4) & 63;
            int c  = idx & 15;
            const bf16* src = mats[mm] + (size_t)(kb + t) * (KVc * Dc) + c * 8;
            uint32_t dst = sb + buf * FT_STAGE + mm * 16384 + (c >> 3) * 8192
                         + SMEM_SWIZZLE_128B(t * 128 + (c & 7) * 16);
            cp_async16(dst, src);
        }
    };

    load_stage(0, 0);
    CP_COMMIT();
    if (NT > 1) { load_stage(1, 1); CP_COMMIT(); }

    int g = lane >> 3;
    int keyl_k = (g >> 1) * 8 + (lane & 7);
    int d16_k  = (g & 1) * 16;
    int keyl_v = (g & 1) * 8 + (lane & 7);
    int dv8    = (g >> 1) * 8;

    for (int kt = 0; kt < NT; kt++) {
        int buf = kt % 3;
        if (kt + 2 < NT) {
            load_stage(kt + 2, (kt + 2) % 3);
            CP_COMMIT();
            CP_WAIT2();
        } else if (kt + 1 < NT) {
            CP_WAIT1();
        } else {
            CP_WAIT0();
        }
        __syncthreads();

        int kb = kt * 64;
        bool active = kb <= qbase + wid * 16 + 15;
        if (active) {
            uint32_t Kh = sb + buf * FT_STAGE;
            uint32_t Kl = Kh + 16384;
            uint32_t Vh = Kh + 32768;
            uint32_t Vl = Kh + 49152;

            float sacc[8][4];
            #pragma unroll
            for (int j = 0; j < 8; j++)
                #pragma unroll
                for (int c = 0; c < 4; c++) sacc[j][c] = 0.f;

            #pragma unroll
            for (int ks = 0; ks < 8; ks++) {
                uint32_t sub = (ks >> 2) * 8192;
                int db = (ks & 3) * 32 + d16_k;
                uint32_t bh[8][2], bl[8][2];
                #pragma unroll
                for (int g4 = 0; g4 < 4; g4++) {
                    uint32_t a = SMEM_SWIZZLE_128B((g4 * 16 + keyl_k) * 128 + db);
                    ldsm4(bh[2 * g4][0], bh[2 * g4][1], bh[2 * g4 + 1][0], bh[2 * g4 + 1][1],
                          Kh + sub + a);
                    ldsm4(bl[2 * g4][0], bl[2 * g4][1], bl[2 * g4 + 1][0], bl[2 * g4 + 1][1],
                          Kl + sub + a);
                }
                #pragma unroll
                for (int j = 0; j < 8; j++) mma16816(sacc[j], qa_hi[ks], bh[j]);
                #pragma unroll
                for (int j = 0; j < 8; j++) mma16816(sacc[j], qa_lo[ks], bh[j]);
                #pragma unroll
                for (int j = 0; j < 8; j++) mma16816(sacc[j], qa_hi[ks], bl[j]);
            }

            if (kb + 64 > qbase + wid * 16) {
                #pragma unroll
                for (int j = 0; j < 8; j++) {
                    int col = kb + j * 8 + (lane & 3) * 2;
                    if (col > r0)     sacc[j][0] = NEG_INF;
                    if (col + 1 > r0) sacc[j][1] = NEG_INF;
                    if (col > r0 + 8)     sacc[j][2] = NEG_INF;
                    if (col + 1 > r0 + 8) sacc[j][3] = NEG_INF;
                }
            }

            float tm0 = NEG_INF, tm1 = NEG_INF;
            #pragma unroll
            for (int j = 0; j < 8; j++) {
                tm0 = fmaxf(tm0, fmaxf(sacc[j][0], sacc[j][1]));
                tm1 = fmaxf(tm1, fmaxf(sacc[j][2], sacc[j][3]));
            }
            tm0 = fmaxf(tm0, __shfl_xor_sync(0xffffffffu, tm0, 1));
            tm0 = fmaxf(tm0, __shfl_xor_sync(0xffffffffu, tm0, 2));
            tm1 = fmaxf(tm1, __shfl_xor_sync(0xffffffffu, tm1, 1));
            tm1 = fmaxf(tm1, __shfl_xor_sync(0xffffffffu, tm1, 2));
            float mn0 = fmaxf(m0, tm0), mn1 = fmaxf(m1, tm1);
            float cor0 = ex2(m0 - mn0), cor1 = ex2(m1 - mn1);
            l0 *= cor0; l1 *= cor1;
            if (m0 != mn0 || m1 != mn1) {
                #pragma unroll
                for (int j = 0; j < 16; j++) {
                    oacc[j][0] *= cor0; oacc[j][1] *= cor0;
                    oacc[j][2] *= cor1; oacc[j][3] *= cor1;
                }
            }
            m0 = mn0; m1 = mn1;

            uint32_t pa_hi[4][4], pa_lo[4][4];
            float ps0 = 0.f, ps1 = 0.f;
            #pragma unroll
            for (int half = 0; half < 2; half++) {
                #pragma unroll
                for (int j = 4 * half; j < 4 * half + 4; j++) {
                    float p0 = ex2(sacc[j][0] - mn0);
                    float p1 = ex2(sacc[j][1] - mn0);
                    float p2 = ex2(sacc[j][2] - mn1);
                    float p3 = ex2(sacc[j][3] - mn1);
                    ps0 += p0 + p1; ps1 += p2 + p3;
                    int kk = j >> 1;
                    int base = (j & 1) ? 2 : 0;
                    split_pack_p(p0, p1, pa_hi[kk][base + 0], pa_lo[kk][base + 0]);
                    split_pack_p(p2, p3, pa_hi[kk][base + 1], pa_lo[kk][base + 1]);
                }
                #pragma unroll
                for (int kk = 2 * half; kk < 2 * half + 2; kk++) {
                    #pragma unroll
                    for (int j = 0; j < 8; j++) {
                        int dd = j * 16 + dv8;
                        uint32_t sub = (dd >> 6) * 8192;
                        uint32_t a = SMEM_SWIZZLE_128B((kk * 16 + keyl_v) * 128 + (dd & 63) * 2);
                        uint32_t vb[2][2];
                        ldsm4t(vb[0][0], vb[0][1], vb[1][0], vb[1][1], Vh + sub + a);
                        mma16816(oacc[2 * j],     pa_hi[kk], vb[0]);
                        mma16816(oacc[2 * j + 1], pa_hi[kk], vb[1]);
                        mma16816(oacc[2 * j],     pa_lo[kk], vb[0]);
                        mma16816(oacc[2 * j + 1], pa_lo[kk], vb[1]);
                        ldsm4t(vb[0][0], vb[0][1], vb[1][0], vb[1][1], Vl + sub + a);
                        mma16816(oacc[2 * j],     pa_hi[kk], vb[0]);
                        mma16816(oacc[2 * j + 1], pa_hi[kk], vb[1]);
                    }
                }
            }
            l0 += ps0; l1 += ps1;
        }
        __syncthreads();
    }

    l0 += __shfl_xor_sync(0xffffffffu, l0, 1);
    l0 += __shfl_xor_sync(0xffffffffu, l0, 2);
    l1 += __shfl_xor_sync(0xffffffffu, l1, 1);
    l1 += __shfl_xor_sync(0xffffffffu, l1, 2);
    float inv0 = 1.0f / l0, inv1 = 1.0f / l1;

    size_t ob0 = (((size_t)b * Sc + r0) * Hc + h) * Dc;
    size_t ob1 = ob0 + (size_t)8 * Hc * Dc;
    #pragma unroll
    for (int j = 0; j < 16; j++) {
        int col = j * 8 + (lane & 3) * 2;
        *(float2*)(ctx + ob0 + col) = make_float2(to_tf32(oacc[j][0] * inv0),
                                                  to_tf32(oacc[j][1] * inv0));
        *(float2*)(ctx + ob1 + col) = make_float2(to_tf32(oacc[j][2] * inv1),
                                                  to_tf32(oacc[j][3] * inv1));
    }
}

// ---------------------------------------------------------------------------
// Launch
// ---------------------------------------------------------------------------
extern "C" void kernel_launch(void* const* d_in, const int* in_sizes, int n_in,
                              void* d_out, int out_size)
{
    const float* hidden = (const float*)d_in[0];
    const float* lnw    = (const float*)d_in[1];
    const float* Wq     = (const float*)d_in[2];
    const float* bq     = (const float*)d_in[3];
    const float* Wk     = (const float*)d_in[4];
    const float* bk     = (const float*)d_in[5];
    const float* Wv     = (const float*)d_in[6];
    const float* bv     = (const float*)d_in[7];
    const float* Wo     = (const float*)d_in[8];
    const float* cosb   = (const float*)d_in[9];
    const float* sinb   = (const float*)d_in[10];
    const float* kc_in  = (const float*)d_in[11];
    const float* vc_in  = (const float*)d_in[12];
    const int*   pos    = (const int*)d_in[13];

    float* out = (float*)d_out;
    const size_t OUTE = (size_t)Bc * Sc * HIDc;
    const size_t CE   = (size_t)Bc * MAXSEQ * KVc * Dc;
    float* kc_out = out + OUTE;
    float* vc_out = kc_out + CE;

    float *h_p, *wqt, *wkt, *wvt, *wot, *ctx_p, *q_p;
    bf16 *khi, *klo, *vhi, *vlo;
    cudaGetSymbolAddress((void**)&h_p, g_h);
    cudaGetSymbolAddress((void**)&wqt, g_wqt);
    cudaGetSymbolAddress((void**)&wkt, g_wkt);
    cudaGetSymbolAddress((void**)&wvt, g_wvt);
    cudaGetSymbolAddress((void**)&wot, g_wot);
    cudaGetSymbolAddress((void**)&ctx_p, g_ctx);
    cudaGetSymbolAddress((void**)&q_p, g_q);
    cudaGetSymbolAddress((void**)&khi, g_khi);
    cudaGetSymbolAddress((void**)&klo, g_klo);
    cudaGetSymbolAddress((void**)&vhi, g_vhi);
    cudaGetSymbolAddress((void**)&vlo, g_vlo);

    cudaFuncSetAttribute(gemm_tf32_kernel, cudaFuncAttributeMaxDynamicSharedMemorySize, GM_SMEM_TOTAL);
    cudaFuncSetAttribute(flash_mma_kernel, cudaFuncAttributeMaxDynamicSharedMemorySize, FT_SMEM);

    const int M = Bc * Sc;

    // 0: rmsnorm (tf32-rounded fp32 out)
    rmsnorm_kernel<<<M, 256>>>(hidden, lnw, h_p);
    // 1: convert Wq
    convert_w_kernel<<<dim3(HIDc / 32, (Hc * Dc) / 32), 256>>>(Wq, wqt, HIDc, Hc * Dc);
    // 2: Q projection + fused RoPE
    gemm_tf32_kernel<<<dim3((Hc * Dc) / 64, M / 128), 256, GM_SMEM_TOTAL>>>(
        h_p, wqt, bq, nullptr, q_p, Hc * Dc, HIDc,
        1, cosb, sinb, nullptr, nullptr, nullptr, nullptr);
    // 3: convert Wk
    convert_w_kernel<<<dim3(HIDc / 32, (KVc * Dc) / 32), 256>>>(Wk, wkt, HIDc, KVc * Dc);
    // 4: K projection + fused RoPE + cache + split
    gemm_tf32_kernel<<<dim3((KVc * Dc) / 64, M / 128), 256, GM_SMEM_TOTAL>>>(
        h_p, wkt, bk, nullptr, nullptr, KVc * Dc, HIDc,
        2, cosb, sinb, pos, kc_out, khi, klo);
    // 5: convert Wv
    convert_w_kernel<<<dim3(HIDc / 32, (KVc * Dc) / 32), 256>>>(Wv, wvt, HIDc, KVc * Dc);
    // 6: V projection + cache + split
    gemm_tf32_kernel<<<dim3((KVc * Dc) / 64, M / 128), 256, GM_SMEM_TOTAL>>>(
        h_p, wvt, bv, nullptr, nullptr, KVc * Dc, HIDc,
        3, nullptr, nullptr, pos, vc_out, vhi, vlo);
    // 7: convert Wo
    convert_w_kernel<<<dim3((Hc * Dc) / 32, HIDc / 32), 256>>>(Wo, wot, Hc * Dc, HIDc);
    // 8: flash attention (bf16 3-term path, fp32 ctx out)
    flash_mma_kernel<<<dim3(Sc / 128, Hc, Bc), 256, FT_SMEM>>>(
        q_p, khi, klo, vhi, vlo, ctx_p);
    // 9: O projection + residual
    gemm_tf32_kernel<<<dim3(HIDc / 64, M / 128), 256, GM_SMEM_TOTAL>>>(
        ctx_p, wot, nullptr, hidden, out, HIDc, HIDc,
        0, nullptr, nullptr, nullptr, nullptr, nullptr, nullptr);
    // cache tail copies (rows [S, MAX_SEQ) only)
    const size_t ROWS = (size_t)KVc * Dc;
    const size_t TAIL = (size_t)(MAXSEQ - Sc) * ROWS;
    for (int b = 0; b < Bc; b++) {
        size_t off = ((size_t)b * MAXSEQ + Sc) * ROWS;
        cudaMemcpyAsync(kc_out + off, kc_in + off, TAIL * sizeof(float), cudaMemcpyDeviceToDevice);
        cudaMemcpyAsync(vc_out + off, vc_in + off, TAIL * sizeof(float), cudaMemcpyDeviceToDevice);
    }
}

// round 15
// speedup vs baseline: 1.2928x; 1.2928x over previous
#include <cuda_runtime.h>
#include <cuda_bf16.h>
#include <cuda_fp16.h>
#include <cstdint>

// Problem constants
#define Bc 2
#define Sc 2048
#define HIDc 2048
#define Hc 16
#define KVc 4
#define Dc 128
#define Gc 4
#define MAXSEQ 4096
#define EPSc 1e-6f
#define NEG_INF (__int_as_float(0xff800000))

typedef __nv_bfloat16 bf16;
typedef __half fp16;

// ---------------------------------------------------------------------------
// Helpers (arch-neutral PTX: ldmatrix / mma.sync bf16+fp16 / cp.async)
// ---------------------------------------------------------------------------
__device__ __forceinline__ uint32_t smem_to_u32(const void* p) {
    uint32_t a;
    asm("{ .reg .u64 t; cvta.to.shared.u64 t, %1; cvt.u32.u64 %0, t; }" : "=r"(a) : "l"(p));
    return a;
}
#define SMEM_SWIZZLE_128B(byte_offset) ((byte_offset) ^ (((byte_offset) >> 3) & 0x70))

__device__ __forceinline__ void cp_async16(uint32_t dst, const void* src) {
    asm volatile("cp.async.cg.shared.global [%0], [%1], 16;" :: "r"(dst), "l"(src));
}
#define CP_COMMIT() asm volatile("cp.async.commit_group;" ::: "memory")
#define CP_WAIT2()  asm volatile("cp.async.wait_group 2;" ::: "memory")
#define CP_WAIT1()  asm volatile("cp.async.wait_group 1;" ::: "memory")
#define CP_WAIT0()  asm volatile("cp.async.wait_group 0;" ::: "memory")

__device__ __forceinline__ void ldsm4(uint32_t& r0, uint32_t& r1, uint32_t& r2, uint32_t& r3,
                                      uint32_t addr) {
    asm volatile("ldmatrix.sync.aligned.m8n8.x4.shared.b16 {%0,%1,%2,%3}, [%4];"
                 : "=r"(r0), "=r"(r1), "=r"(r2), "=r"(r3) : "r"(addr));
}
__device__ __forceinline__ void ldsm4t(uint32_t& r0, uint32_t& r1, uint32_t& r2, uint32_t& r3,
                                       uint32_t addr) {
    asm volatile("ldmatrix.sync.aligned.m8n8.x4.trans.shared.b16 {%0,%1,%2,%3}, [%4];"
                 : "=r"(r0), "=r"(r1), "=r"(r2), "=r"(r3) : "r"(addr));
}
__device__ __forceinline__ void mma16816(float* c, const uint32_t* a, const uint32_t* b) {
    asm volatile("mma.sync.aligned.m16n8k16.row.col.f32.bf16.bf16.f32 "
                 "{%0,%1,%2,%3}, {%4,%5,%6,%7}, {%8,%9}, {%0,%1,%2,%3};"
                 : "+f"(c[0]), "+f"(c[1]), "+f"(c[2]), "+f"(c[3])
                 : "r"(a[0]), "r"(a[1]), "r"(a[2]), "r"(a[3]), "r"(b[0]), "r"(b[1]));
}
__device__ __forceinline__ void mma16816h(float* c, const uint32_t* a, const uint32_t* b) {
    asm volatile("mma.sync.aligned.m16n8k16.row.col.f32.f16.f16.f32 "
                 "{%0,%1,%2,%3}, {%4,%5,%6,%7}, {%8,%9}, {%0,%1,%2,%3};"
                 : "+f"(c[0]), "+f"(c[1]), "+f"(c[2]), "+f"(c[3])
                 : "r"(a[0]), "r"(a[1]), "r"(a[2]), "r"(a[3]), "r"(b[0]), "r"(b[1]));
}
__device__ __forceinline__ float ex2(float x) {
    float y;
    asm("ex2.approx.f32 %0, %1;" : "=f"(y) : "f"(x));
    return y;
}
// bf16 hi/lo split (flash K/V path)
__device__ __forceinline__ void split_pack(float x, float y, uint32_t& hi, uint32_t& lo) {
    bf16 xh = __float2bfloat16(x);
    bf16 yh = __float2bfloat16(y);
    float xl = x - __bfloat162float(xh);
    float yl = y - __bfloat162float(yh);
    __nv_bfloat162 H; H.x = xh; H.y = yh;
    __nv_bfloat162 L = __floats2bfloat162_rn(xl, yl);
    hi = *(uint32_t*)&H;
    lo = *(uint32_t*)&L;
}
// fp16 hi/lo split (GEMM A operands)
__device__ __forceinline__ void split_pack_h(float x, float y, uint32_t& hi, uint32_t& lo) {
    fp16 xh = __float2half_rn(x);
    fp16 yh = __float2half_rn(y);
    float xl = x - __half2float(xh);
    float yl = y - __half2float(yh);
    __half2 H = __halves2half2(xh, yh);
    __half2 L = __floats2half2_rn(xl, yl);
    hi = *(uint32_t*)&H;
    lo = *(uint32_t*)&L;
}
// cheap truncation-based split for nonneg softmax probs
__device__ __forceinline__ void split_pack_p(float x, float y, uint32_t& hi, uint32_t& lo) {
    uint32_t xb = __float_as_uint(x), yb = __float_as_uint(y);
    hi = __byte_perm(xb, yb, 0x7632);
    float xl = x - __uint_as_float(xb & 0xFFFF0000u);
    float yl = y - __uint_as_float(yb & 0xFFFF0000u);
    lo = __byte_perm(__float_as_uint(xl), __float_as_uint(yl), 0x7632);
}

// ---------------------------------------------------------------------------
// Device scratch
// ---------------------------------------------------------------------------
__device__ fp16 g_hhi[(size_t)4096 * 2048];
__device__ fp16 g_hlo[(size_t)4096 * 2048];
__device__ fp16 g_wqt[(size_t)2048 * 2048];
__device__ fp16 g_wkt[(size_t)512 * 2048];
__device__ fp16 g_wvt[(size_t)512 * 2048];
__device__ fp16 g_wot[(size_t)2048 * 2048];
__device__ fp16 g_ctx_hi[(size_t)4096 * 2048];
__device__ fp16 g_ctx_lo[(size_t)4096 * 2048];
__device__ float g_q[(size_t)4096 * 2048];
__device__ bf16 g_khi[(size_t)Bc * Sc * KVc * Dc];
__device__ bf16 g_klo[(size_t)Bc * Sc * KVc * Dc];
__device__ bf16 g_vhi[(size_t)Bc * Sc * KVc * Dc];
__device__ bf16 g_vlo[(size_t)Bc * Sc * KVc * Dc];

// ---------------------------------------------------------------------------
// RMSNorm fused with fp16 hi/lo split output
// ---------------------------------------------------------------------------
__global__ void __launch_bounds__(256) rmsnorm_split_kernel(
    const float* __restrict__ x, const float* __restrict__ w,
    fp16* __restrict__ hhi, fp16* __restrict__ hlo)
{
    int row = blockIdx.x;
    const float* xr = x + (size_t)row * HIDc;
    float ss = 0.f;
    for (int i = threadIdx.x * 4; i < HIDc; i += 1024) {
        float4 t = *(const float4*)(xr + i);
        ss += t.x * t.x + t.y * t.y + t.z * t.z + t.w * t.w;
    }
    #pragma unroll
    for (int o = 16; o > 0; o >>= 1) ss += __shfl_xor_sync(0xffffffffu, ss, o);
    __shared__ float red[8];
    if ((threadIdx.x & 31) == 0) red[threadIdx.x >> 5] = ss;
    __syncthreads();
    float tot = red[0] + red[1] + red[2] + red[3] + red[4] + red[5] + red[6] + red[7];
    float inv = rsqrtf(tot * (1.0f / HIDc) + EPSc);
    fp16* hh = hhi + (size_t)row * HIDc;
    fp16* hl = hlo + (size_t)row * HIDc;
    for (int i = threadIdx.x * 2; i < HIDc; i += 512) {
        float2 t = *(const float2*)(xr + i);
        float2 wv = *(const float2*)(w + i);
        uint32_t hh32, ll32;
        split_pack_h(t.x * inv * wv.x, t.y * inv * wv.y, hh32, ll32);
        *(uint32_t*)(hh + i) = hh32;
        *(uint32_t*)(hl + i) = ll32;
    }
}

// ---------------------------------------------------------------------------
// Weight convert + transpose: W fp32 [K,N] -> Wt fp16 [N,K]
// ---------------------------------------------------------------------------
__global__ void __launch_bounds__(256) convert_w_kernel(
    const float* __restrict__ W, fp16* __restrict__ Wt, int K, int N)
{
    __shared__ float t[32][33];
    int k0 = blockIdx.x * 32;
    int n0 = blockIdx.y * 32;
    int tx = threadIdx.x & 31;
    int ty = threadIdx.x >> 5;
    #pragma unroll
    for (int j = 0; j < 4; j++) {
        int r = ty + 8 * j;
        t[r][tx] = W[(size_t)(k0 + r) * N + n0 + tx];
    }
    __syncthreads();
    #pragma unroll
    for (int j = 0; j < 4; j++) {
        int r = ty + 8 * j;
        Wt[(size_t)(n0 + r) * K + k0 + tx] = __float2half_rn(t[tx][r]);
    }
}

// ---------------------------------------------------------------------------
// fp16 2-term GEMM, 128(M)x64(N), BK=64, 2-stage, 2 CTAs/SM.
// acc = Ahi*B + Alo*B  (== exact-A x fp16-rounded-B; error ~2^-12)
// Stage = Ahi(16K) + Alo(16K) + B(8K) = 40KB; 2 stages = 80KB.
// Fused epilogue modes (same as R13):
//   0: C = acc (+res); 1: C = rope(acc+bias) fp32;
//   2: rope(acc+bias) -> cache fp32 + split-bf16; 3: (acc+bias) -> cache + split-bf16.
// ---------------------------------------------------------------------------
#define GA_BYTES 16384
#define GB_BYTES 8192
#define G_STAGE  40960
#define GM_SMEM_TOTAL (2 * G_STAGE)   // 81920

__global__ void __launch_bounds__(256, 2) gemm_fp16_kernel(
    const fp16* __restrict__ Ahi, const fp16* __restrict__ Alo,
    const fp16* __restrict__ B,
    const float* __restrict__ bias, const float* __restrict__ res,
    float* __restrict__ C, int N, int K,
    int mode,
    const float* __restrict__ cosb, const float* __restrict__ sinb,
    const int* __restrict__ pos,
    float* __restrict__ cacheOut, bf16* __restrict__ shi, bf16* __restrict__ slo)
{
    extern __shared__ char smem[];
    uint32_t sb = smem_to_u32(smem);
    int tid  = threadIdx.x;
    int wid  = tid >> 5;
    int lane = tid & 31;
    int rowBase = blockIdx.y * 128;
    int colBase = blockIdx.x * 64;

    int wm = wid & 3;
    int wn = wid >> 2;
    int wmBase = wm * 32;
    int wnBase = wn * 32;

    const fp16* gA0 = Ahi + (size_t)rowBase * K;
    const fp16* gA1 = Alo + (size_t)rowBase * K;
    const fp16* gB  = B  + (size_t)colBase * K;

    float acc[2][4][4];
    #pragma unroll
    for (int i = 0; i < 2; i++)
        #pragma unroll
        for (int j = 0; j < 4; j++)
            #pragma unroll
            for (int c = 0; c < 4; c++) acc[i][j][c] = 0.f;

    const int KT = K >> 6;

    auto load_stage = [&](int kt, int buf) {
        uint32_t base = sb + buf * G_STAGE;
        int kOff = kt * 64;
        #pragma unroll
        for (int i = 0; i < 4; i++) {
            int c = tid + i * 256;
            size_t g = (size_t)(c >> 3) * K + kOff + (c & 7) * 8;
            uint32_t so = SMEM_SWIZZLE_128B((uint32_t)((c >> 3) * 128 + (c & 7) * 16));
            cp_async16(base + so, gA0 + g);
            cp_async16(base + GA_BYTES + so, gA1 + g);
        }
        #pragma unroll
        for (int i = 0; i < 2; i++) {
            int c = tid + i * 256;
            size_t g = (size_t)(c >> 3) * K + kOff + (c & 7) * 8;
            uint32_t so = SMEM_SWIZZLE_128B((uint32_t)((c >> 3) * 128 + (c & 7) * 16));
            cp_async16(base + 2 * GA_BYTES + so, gB + g);
        }
    };

    load_stage(0, 0);
    CP_COMMIT();

    int aRow = wmBase + (lane & 15);
    int aKs  = (lane >> 4) << 4;
    int bRow = wnBase + ((lane >> 4) << 3) + (lane & 7);
    int bKs  = ((lane >> 3) & 1) << 4;

    for (int kt = 0; kt < KT; kt++) {
        int buf = kt & 1;
        if (kt + 1 < KT) {
            load_stage(kt + 1, buf ^ 1);
            CP_COMMIT();
            CP_WAIT1();
        } else {
            CP_WAIT0();
        }
        __syncthreads();

        uint32_t mb = sb + buf * G_STAGE;
        uint32_t mbA0 = mb;
        uint32_t mbA1 = mb + GA_BYTES;
        uint32_t mbB  = mb + 2 * GA_BYTES;
        #pragma unroll
        for (int ks = 0; ks < 4; ks++) {
            int kb = ks * 32;
            uint32_t aA[2][4], aC[2][4], bB[4][2];
            #pragma unroll
            for (int i = 0; i < 2; i++)
                ldsm4(aA[i][0], aA[i][1], aA[i][2], aA[i][3],
                      mbA0 + SMEM_SWIZZLE_128B((aRow + i * 16) * 128 + kb + aKs));
            #pragma unroll
            for (int j = 0; j < 2; j++)
                ldsm4(bB[2 * j][0], bB[2 * j][1], bB[2 * j + 1][0], bB[2 * j + 1][1],
                      mbB + SMEM_SWIZZLE_128B((bRow + j * 16) * 128 + kb + bKs));
            #pragma unroll
            for (int i = 0; i < 2; i++)
                #pragma unroll
                for (int j = 0; j < 4; j++) mma16816h(acc[i][j], aA[i], bB[j]);
            #pragma unroll
            for (int i = 0; i < 2; i++)
                ldsm4(aC[i][0], aC[i][1], aC[i][2], aC[i][3],
                      mbA1 + SMEM_SWIZZLE_128B((aRow + i * 16) * 128 + kb + aKs));
            #pragma unroll
            for (int i = 0; i < 2; i++)
                #pragma unroll
                for (int j = 0; j < 4; j++) mma16816h(acc[i][j], aC[i], bB[j]);
        }
        __syncthreads();
    }

    // ---- fused epilogue ----
    #pragma unroll
    for (int i = 0; i < 2; i++) {
        #pragma unroll
        for (int j = 0; j < 4; j++) {
            int col = colBase + wnBase + j * 8 + (lane & 3) * 2;   // even
            int r0 = rowBase + wmBase + i * 16 + (lane >> 2);
            int r1 = r0 + 8;
            float b0 = 0.f, b1 = 0.f;
            if (bias) { b0 = __ldg(bias + col); b1 = __ldg(bias + col + 1); }
            float v0 = acc[i][j][0] + b0, v1 = acc[i][j][1] + b1;
            float v2 = acc[i][j][2] + b0, v3 = acc[i][j][3] + b1;
            if (res) {
                const float* p0 = res + (size_t)r0 * N + col;
                const float* p1 = res + (size_t)r1 * N + col;
                v0 += p0[0]; v1 += p0[1];
                v2 += p1[0]; v3 += p1[1];
            }
            if (mode == 1 || mode == 2) {
                int d = col & (Dc - 1);
                float c0 = __ldg(cosb + (size_t)r0 * Dc + d);
                float s0 = __ldg(sinb + (size_t)r0 * Dc + d);
                float c1 = __ldg(cosb + (size_t)r1 * Dc + d);
                float s1 = __ldg(sinb + (size_t)r1 * Dc + d);
                float t0 = v0 * c0 - v1 * s0; v1 = v1 * c0 + v0 * s0; v0 = t0;
                float t2 = v2 * c1 - v3 * s1; v3 = v3 * c1 + v2 * s1; v2 = t2;
            }
            if (mode <= 1) {
                *(float2*)(C + (size_t)r0 * N + col) = make_float2(v0, v1);
                *(float2*)(C + (size_t)r1 * N + col) = make_float2(v2, v3);
            } else {
                int s0i = r0 & (Sc - 1), bb0 = r0 >> 11;
                int s1i = r1 & (Sc - 1), bb1 = r1 >> 11;
                int p0 = __ldg(pos + s0i);
                int p1 = __ldg(pos + s1i);
                *(float2*)(cacheOut + ((size_t)bb0 * MAXSEQ + p0) * N + col) = make_float2(v0, v1);
                *(float2*)(cacheOut + ((size_t)bb1 * MAXSEQ + p1) * N + col) = make_float2(v2, v3);
                uint32_t hh, ll;
                split_pack(v0, v1, hh, ll);
                *(uint32_t*)(shi + (size_t)r0 * N + col) = hh;
                *(uint32_t*)(slo + (size_t)r0 * N + col) = ll;
                split_pack(v2, v3, hh, ll);
                *(uint32_t*)(shi + (size_t)r1 * N + col) = hh;
                *(uint32_t*)(slo + (size_t)r1 * N + col) = ll;
            }
        }
    }
}

// ---------------------------------------------------------------------------
// Tensor-core flash attention (bf16 3-term, unchanged math; emits fp16 ctx hi/lo)
// ---------------------------------------------------------------------------
#define FT_STAGE 65536
#define FT_SMEM (3 * FT_STAGE)   // 196608

__global__ void __launch_bounds__(256, 1) flash_mma_kernel(
    const float* __restrict__ q,
    const bf16* __restrict__ khi, const bf16* __restrict__ klo,
    const bf16* __restrict__ vhi, const bf16* __restrict__ vlo,
    fp16* __restrict__ ohi, fp16* __restrict__ olo)
{
    extern __shared__ char smem[];
    uint32_t sb = smem_to_u32(smem);
    int qt = gridDim.x - 1 - blockIdx.x;
    int h = blockIdx.y, b = blockIdx.z;
    int kvh = h >> 2;
    int tid = threadIdx.x, wid = tid >> 5, lane = tid & 31;
    int qbase = qt * 128;
    int r0 = qbase + wid * 16 + (lane >> 2);

    const float scale = 0.08838834764831845f * 1.4426950408889634f;

    uint32_t qa_hi[8][4], qa_lo[8][4];
    {
        const float* q0 = q + (((size_t)b * Sc + r0) * Hc + h) * Dc;
        const float* q1 = q0 + (size_t)8 * Hc * Dc;
        #pragma unroll
        for (int kk = 0; kk < 8; kk++) {
            int c0 = kk * 16 + (lane & 3) * 2;
            split_pack(q0[c0] * scale, q0[c0 + 1] * scale, qa_hi[kk][0], qa_lo[kk][0]);
            split_pack(q1[c0] * scale, q1[c0 + 1] * scale, qa_hi[kk][1], qa_lo[kk][1]);
            split_pack(q0[c0 + 8] * scale, q0[c0 + 9] * scale, qa_hi[kk][2], qa_lo[kk][2]);
            split_pack(q1[c0 + 8] * scale, q1[c0 + 9] * scale, qa_hi[kk][3], qa_lo[kk][3]);
        }
    }

    float oacc[16][4];
    #pragma unroll
    for (int j = 0; j < 16; j++)
        #pragma unroll
        for (int c = 0; c < 4; c++) oacc[j][c] = 0.f;
    float m0 = NEG_INF, m1 = NEG_INF, l0 = 0.f, l1 = 0.f;

    const bf16* mats[4];
    {
        size_t off = (size_t)b * Sc * KVc * Dc + (size_t)kvh * Dc;
        mats[0] = khi + off; mats[1] = klo + off; mats[2] = vhi + off; mats[3] = vlo + off;
    }

    const int NT = 2 * qt + 2;

    auto load_stage = [&](int kt, int buf) {
        int kb = kt * 64;
        #pragma unroll
        for (int i = 0; i < 16; i++) {
            int idx = tid + i * 256;
            int mm = idx >> 10;
            int t  = (idx >> 4) & 63;
            int c  = idx & 15;
            const bf16* src = mats[mm] + (size_t)(kb + t) * (KVc * Dc) + c * 8;
            uint32_t dst = sb + buf * FT_STAGE + mm * 16384 + (c >> 3) * 8192
                         + SMEM_SWIZZLE_128B(t * 128 + (c & 7) * 16);
            cp_async16(dst, src);
        }
    };

    load_stage(0, 0);
    CP_COMMIT();
    if (NT > 1) { load_stage(1, 1); CP_COMMIT(); }

    int g = lane >> 3;
    int keyl_k = (g >> 1) * 8 + (lane & 7);
    int d16_k  = (g & 1) * 16;
    int keyl_v = (g & 1) * 8 + (lane & 7);
    int dv8    = (g >> 1) * 8;

    for (int kt = 0; kt < NT; kt++) {
        int buf = kt % 3;
        if (kt + 2 < NT) {
            load_stage(kt + 2, (kt + 2) % 3);
            CP_COMMIT();
            CP_WAIT2();
        } else if (kt + 1 < NT) {
            CP_WAIT1();
        } else {
            CP_WAIT0();
        }
        __syncthreads();

        int kb = kt * 64;
        bool active = kb <= qbase + wid * 16 + 15;
        if (active) {
            uint32_t Kh = sb + buf * FT_STAGE;
            uint32_t Kl = Kh + 16384;
            uint32_t Vh = Kh + 32768;
            uint32_t Vl = Kh + 49152;

            float sacc[8][4];
            #pragma unroll
            for (int j = 0; j < 8; j++)
                #pragma unroll
                for (int c = 0; c < 4; c++) sacc[j][c] = 0.f;

            #pragma unroll
            for (int ks = 0; ks < 8; ks++) {
                uint32_t sub = (ks >> 2) * 8192;
                int db = (ks & 3) * 32 + d16_k;
                uint32_t bh[8][2], bl[8][2];
                #pragma unroll
                for (int g4 = 0; g4 < 4; g4++) {
                    uint32_t a = SMEM_SWIZZLE_128B((g4 * 16 + keyl_k) * 128 + db);
                    ldsm4(bh[2 * g4][0], bh[2 * g4][1], bh[2 * g4 + 1][0], bh[2 * g4 + 1][1],
                          Kh + sub + a);
                    ldsm4(bl[2 * g4][0], bl[2 * g4][1], bl[2 * g4 + 1][0], bl[2 * g4 + 1][1],
                          Kl + sub + a);
                }
                #pragma unroll
                for (int j = 0; j < 8; j++) mma16816(sacc[j], qa_hi[ks], bh[j]);
                #pragma unroll
                for (int j = 0; j < 8; j++) mma16816(sacc[j], qa_lo[ks], bh[j]);
                #pragma unroll
                for (int j = 0; j < 8; j++) mma16816(sacc[j], qa_hi[ks], bl[j]);
            }

            if (kb + 64 > qbase + wid * 16) {
                #pragma unroll
                for (int j = 0; j < 8; j++) {
                    int col = kb + j * 8 + (lane & 3) * 2;
                    if (col > r0)     sacc[j][0] = NEG_INF;
                    if (col + 1 > r0) sacc[j][1] = NEG_INF;
                    if (col > r0 + 8)     sacc[j][2] = NEG_INF;
                    if (col + 1 > r0 + 8) sacc[j][3] = NEG_INF;
                }
            }

            float tm0 = NEG_INF, tm1 = NEG_INF;
            #pragma unroll
            for (int j = 0; j < 8; j++) {
                tm0 = fmaxf(tm0, fmaxf(sacc[j][0], sacc[j][1]));
                tm1 = fmaxf(tm1, fmaxf(sacc[j][2], sacc[j][3]));
            }
            tm0 = fmaxf(tm0, __shfl_xor_sync(0xffffffffu, tm0, 1));
            tm0 = fmaxf(tm0, __shfl_xor_sync(0xffffffffu, tm0, 2));
            tm1 = fmaxf(tm1, __shfl_xor_sync(0xffffffffu, tm1, 1));
            tm1 = fmaxf(tm1, __shfl_xor_sync(0xffffffffu, tm1, 2));
            float mn0 = fmaxf(m0, tm0), mn1 = fmaxf(m1, tm1);
            float cor0 = ex2(m0 - mn0), cor1 = ex2(m1 - mn1);
            l0 *= cor0; l1 *= cor1;
            if (m0 != mn0 || m1 != mn1) {
                #pragma unroll
                for (int j = 0; j < 16; j++) {
                    oacc[j][0] *= cor0; oacc[j][1] *= cor0;
                    oacc[j][2] *= cor1; oacc[j][3] *= cor1;
                }
            }
            m0 = mn0; m1 = mn1;

            uint32_t pa_hi[4][4], pa_lo[4][4];
            float ps0 = 0.f, ps1 = 0.f;
            #pragma unroll
            for (int half = 0; half < 2; half++) {
                #pragma unroll
                for (int j = 4 * half; j < 4 * half + 4; j++) {
                    float p0 = ex2(sacc[j][0] - mn0);
                    float p1 = ex2(sacc[j][1] - mn0);
                    float p2 = ex2(sacc[j][2] - mn1);
                    float p3 = ex2(sacc[j][3] - mn1);
                    ps0 += p0 + p1; ps1 += p2 + p3;
                    int kk = j >> 1;
                    int base = (j & 1) ? 2 : 0;
                    split_pack_p(p0, p1, pa_hi[kk][base + 0], pa_lo[kk][base + 0]);
                    split_pack_p(p2, p3, pa_hi[kk][base + 1], pa_lo[kk][base + 1]);
                }
                #pragma unroll
                for (int kk = 2 * half; kk < 2 * half + 2; kk++) {
                    #pragma unroll
                    for (int j = 0; j < 8; j++) {
                        int dd = j * 16 + dv8;
                        uint32_t sub = (dd >> 6) * 8192;
                        uint32_t a = SMEM_SWIZZLE_128B((kk * 16 + keyl_v) * 128 + (dd & 63) * 2);
                        uint32_t vb[2][2];
                        ldsm4t(vb[0][0], vb[0][1], vb[1][0], vb[1][1], Vh + sub + a);
                        mma16816(oacc[2 * j],     pa_hi[kk], vb[0]);
                        mma16816(oacc[2 * j + 1], pa_hi[kk], vb[1]);
                        mma16816(oacc[2 * j],     pa_lo[kk], vb[0]);
                        mma16816(oacc[2 * j + 1], pa_lo[kk], vb[1]);
                        ldsm4t(vb[0][0], vb[0][1], vb[1][0], vb[1][1], Vl + sub + a);
                        mma16816(oacc[2 * j],     pa_hi[kk], vb[0]);
                        mma16816(oacc[2 * j + 1], pa_hi[kk], vb[1]);
                    }
                }
            }
            l0 += ps0; l1 += ps1;
        }
        __syncthreads();
    }

    l0 += __shfl_xor_sync(0xffffffffu, l0, 1);
    l0 += __shfl_xor_sync(0xffffffffu, l0, 2);
    l1 += __shfl_xor_sync(0xffffffffu, l1, 1);
    l1 += __shfl_xor_sync(0xffffffffu, l1, 2);
    float inv0 = 1.0f / l0, inv1 = 1.0f / l1;

    size_t ob0 = (((size_t)b * Sc + r0) * Hc + h) * Dc;
    size_t ob1 = ob0 + (size_t)8 * Hc * Dc;
    #pragma unroll
    for (int j = 0; j < 16; j++) {
        int col = j * 8 + (lane & 3) * 2;
        uint32_t hh, ll;
        split_pack_h(oacc[j][0] * inv0, oacc[j][1] * inv0, hh, ll);
        *(uint32_t*)(ohi + ob0 + col) = hh;
        *(uint32_t*)(olo + ob0 + col) = ll;
        split_pack_h(oacc[j][2] * inv1, oacc[j][3] * inv1, hh, ll);
        *(uint32_t*)(ohi + ob1 + col) = hh;
        *(uint32_t*)(olo + ob1 + col) = ll;
    }
}

// ---------------------------------------------------------------------------
// Launch (single stream, R13 fused-epilogue structure)
// ---------------------------------------------------------------------------
extern "C" void kernel_launch(void* const* d_in, const int* in_sizes, int n_in,
                              void* d_out, int out_size)
{
    const float* hidden = (const float*)d_in[0];
    const float* lnw    = (const float*)d_in[1];
    const float* Wq     = (const float*)d_in[2];
    const float* bq     = (const float*)d_in[3];
    const float* Wk     = (const float*)d_in[4];
    const float* bk     = (const float*)d_in[5];
    const float* Wv     = (const float*)d_in[6];
    const float* bv     = (const float*)d_in[7];
    const float* Wo     = (const float*)d_in[8];
    const float* cosb   = (const float*)d_in[9];
    const float* sinb   = (const float*)d_in[10];
    const float* kc_in  = (const float*)d_in[11];
    const float* vc_in  = (const float*)d_in[12];
    const int*   pos    = (const int*)d_in[13];

    float* out = (float*)d_out;
    const size_t OUTE = (size_t)Bc * Sc * HIDc;
    const size_t CE   = (size_t)Bc * MAXSEQ * KVc * Dc;
    float* kc_out = out + OUTE;
    float* vc_out = kc_out + CE;

    fp16 *hhi, *hlo, *wqt, *wkt, *wvt, *wot, *ctx_hi, *ctx_lo;
    bf16 *khi, *klo, *vhi, *vlo;
    float *q_p;
    cudaGetSymbolAddress((void**)&hhi, g_hhi);
    cudaGetSymbolAddress((void**)&hlo, g_hlo);
    cudaGetSymbolAddress((void**)&wqt, g_wqt);
    cudaGetSymbolAddress((void**)&wkt, g_wkt);
    cudaGetSymbolAddress((void**)&wvt, g_wvt);
    cudaGetSymbolAddress((void**)&wot, g_wot);
    cudaGetSymbolAddress((void**)&ctx_hi, g_ctx_hi);
    cudaGetSymbolAddress((void**)&ctx_lo, g_ctx_lo);
    cudaGetSymbolAddress((void**)&khi, g_khi);
    cudaGetSymbolAddress((void**)&klo, g_klo);
    cudaGetSymbolAddress((void**)&vhi, g_vhi);
    cudaGetSymbolAddress((void**)&vlo, g_vlo);
    cudaGetSymbolAddress((void**)&q_p, g_q);

    cudaFuncSetAttribute(gemm_fp16_kernel, cudaFuncAttributeMaxDynamicSharedMemorySize, GM_SMEM_TOTAL);
    cudaFuncSetAttribute(flash_mma_kernel, cudaFuncAttributeMaxDynamicSharedMemorySize, FT_SMEM);

    const int M = Bc * Sc;

    // 0: rmsnorm (fp16 hi/lo out)
    rmsnorm_split_kernel<<<M, 256>>>(hidden, lnw, hhi, hlo);
    // 1: convert Wq
    convert_w_kernel<<<dim3(HIDc / 32, (Hc * Dc) / 32), 256>>>(Wq, wqt, HIDc, Hc * Dc);
    // 2: Q projection + fused RoPE
    gemm_fp16_kernel<<<dim3((Hc * Dc) / 64, M / 128), 256, GM_SMEM_TOTAL>>>(
        hhi, hlo, wqt, bq, nullptr, q_p, Hc * Dc, HIDc,
        1, cosb, sinb, nullptr, nullptr, nullptr, nullptr);
    // 3: convert Wk
    convert_w_kernel<<<dim3(HIDc / 32, (KVc * Dc) / 32), 256>>>(Wk, wkt, HIDc, KVc * Dc);
    // 4: K projection + fused RoPE + cache + bf16 split
    gemm_fp16_kernel<<<dim3((KVc * Dc) / 64, M / 128), 256, GM_SMEM_TOTAL>>>(
        hhi, hlo, wkt, bk, nullptr, nullptr, KVc * Dc, HIDc,
        2, cosb, sinb, pos, kc_out, khi, klo);
    // 5: convert Wv
    convert_w_kernel<<<dim3(HIDc / 32, (KVc * Dc) / 32), 256>>>(Wv, wvt, HIDc, KVc * Dc);
    // 6: V projection + cache + bf16 split
    gemm_fp16_kernel<<<dim3((KVc * Dc) / 64, M / 128), 256, GM_SMEM_TOTAL>>>(
        hhi, hlo, wvt, bv, nullptr, nullptr, KVc * Dc, HIDc,
        3, nullptr, nullptr, pos, vc_out, vhi, vlo);
    // 7: convert Wo
    convert_w_kernel<<<dim3((Hc * Dc) / 32, HIDc / 32), 256>>>(Wo, wot, Hc * Dc, HIDc);
    // 8: flash attention (bf16 3-term, fp16 ctx hi/lo out)
    flash_mma_kernel<<<dim3(Sc / 128, Hc, Bc), 256, FT_SMEM>>>(
        q_p, khi, klo, vhi, vlo, ctx_hi, ctx_lo);
    // 9: O projection + residual
    gemm_fp16_kernel<<<dim3(HIDc / 64, M / 128), 256, GM_SMEM_TOTAL>>>(
        ctx_hi, ctx_lo, wot, nullptr, hidden, out, HIDc, HIDc,
        0, nullptr, nullptr, nullptr, nullptr, nullptr, nullptr);
    // cache tail copies (rows [S, MAX_SEQ) only)
    const size_t ROWS = (size_t)KVc * Dc;
    const size_t TAIL = (size_t)(MAXSEQ - Sc) * ROWS;
    for (int b = 0; b < Bc; b++) {
        size_t off = ((size_t)b * MAXSEQ + Sc) * ROWS;
        cudaMemcpyAsync(kc_out + off, kc_in + off, TAIL * sizeof(float), cudaMemcpyDeviceToDevice);
        cudaMemcpyAsync(vc_out + off, vc_in + off, TAIL * sizeof(float), cudaMemcpyDeviceToDevice);
    }
}

// round 16
// speedup vs baseline: 1.4416x; 1.1151x over previous
#include <cuda_runtime.h>
#include <cuda_bf16.h>
#include <cuda_fp16.h>
#include <cstdint>

// Problem constants
#define Bc 2
#define Sc 2048
#define HIDc 2048
#define Hc 16
#define KVc 4
#define Dc 128
#define Gc 4
#define MAXSEQ 4096
#define EPSc 1e-6f
#define NEG_INF (__int_as_float(0xff800000))

typedef __nv_bfloat16 bf16;
typedef __half fp16;

// ---------------------------------------------------------------------------
// Helpers (arch-neutral PTX: ldmatrix / mma.sync fp16 / cp.async)
// ---------------------------------------------------------------------------
__device__ __forceinline__ uint32_t smem_to_u32(const void* p) {
    uint32_t a;
    asm("{ .reg .u64 t; cvta.to.shared.u64 t, %1; cvt.u32.u64 %0, t; }" : "=r"(a) : "l"(p));
    return a;
}
#define SMEM_SWIZZLE_128B(byte_offset) ((byte_offset) ^ (((byte_offset) >> 3) & 0x70))

__device__ __forceinline__ void cp_async16(uint32_t dst, const void* src) {
    asm volatile("cp.async.cg.shared.global [%0], [%1], 16;" :: "r"(dst), "l"(src));
}
#define CP_COMMIT() asm volatile("cp.async.commit_group;" ::: "memory")
#define CP_WAIT2()  asm volatile("cp.async.wait_group 2;" ::: "memory")
#define CP_WAIT1()  asm volatile("cp.async.wait_group 1;" ::: "memory")
#define CP_WAIT0()  asm volatile("cp.async.wait_group 0;" ::: "memory")

__device__ __forceinline__ void ldsm4(uint32_t& r0, uint32_t& r1, uint32_t& r2, uint32_t& r3,
                                      uint32_t addr) {
    asm volatile("ldmatrix.sync.aligned.m8n8.x4.shared.b16 {%0,%1,%2,%3}, [%4];"
                 : "=r"(r0), "=r"(r1), "=r"(r2), "=r"(r3) : "r"(addr));
}
__device__ __forceinline__ void ldsm4t(uint32_t& r0, uint32_t& r1, uint32_t& r2, uint32_t& r3,
                                       uint32_t addr) {
    asm volatile("ldmatrix.sync.aligned.m8n8.x4.trans.shared.b16 {%0,%1,%2,%3}, [%4];"
                 : "=r"(r0), "=r"(r1), "=r"(r2), "=r"(r3) : "r"(addr));
}
__device__ __forceinline__ void mma16816h(float* c, const uint32_t* a, const uint32_t* b) {
    asm volatile("mma.sync.aligned.m16n8k16.row.col.f32.f16.f16.f32 "
                 "{%0,%1,%2,%3}, {%4,%5,%6,%7}, {%8,%9}, {%0,%1,%2,%3};"
                 : "+f"(c[0]), "+f"(c[1]), "+f"(c[2]), "+f"(c[3])
                 : "r"(a[0]), "r"(a[1]), "r"(a[2]), "r"(a[3]), "r"(b[0]), "r"(b[1]));
}
__device__ __forceinline__ float ex2(float x) {
    float y;
    asm("ex2.approx.f32 %0, %1;" : "=f"(y) : "f"(x));
    return y;
}
// fp16 hi/lo split
__device__ __forceinline__ void split_pack_h(float x, float y, uint32_t& hi, uint32_t& lo) {
    fp16 xh = __float2half_rn(x);
    fp16 yh = __float2half_rn(y);
    float xl = x - __half2float(xh);
    float yl = y - __half2float(yh);
    __half2 H = __halves2half2(xh, yh);
    __half2 L = __floats2half2_rn(xl, yl);
    hi = *(uint32_t*)&H;
    lo = *(uint32_t*)&L;
}

// ---------------------------------------------------------------------------
// Device scratch
// ---------------------------------------------------------------------------
__device__ fp16 g_hhi[(size_t)4096 * 2048];
__device__ fp16 g_hlo[(size_t)4096 * 2048];
__device__ fp16 g_wqt[(size_t)2048 * 2048];
__device__ fp16 g_wkt[(size_t)512 * 2048];
__device__ fp16 g_wvt[(size_t)512 * 2048];
__device__ fp16 g_wot[(size_t)2048 * 2048];
__device__ fp16 g_ctx_hi[(size_t)4096 * 2048];
__device__ fp16 g_ctx_lo[(size_t)4096 * 2048];
__device__ float g_q[(size_t)4096 * 2048];
__device__ fp16 g_khf[(size_t)Bc * Sc * KVc * Dc];
__device__ fp16 g_vhf[(size_t)Bc * Sc * KVc * Dc];

// ---------------------------------------------------------------------------
// RMSNorm fused with fp16 hi/lo split output
// ---------------------------------------------------------------------------
__global__ void __launch_bounds__(256) rmsnorm_split_kernel(
    const float* __restrict__ x, const float* __restrict__ w,
    fp16* __restrict__ hhi, fp16* __restrict__ hlo)
{
    int row = blockIdx.x;
    const float* xr = x + (size_t)row * HIDc;
    float ss = 0.f;
    for (int i = threadIdx.x * 4; i < HIDc; i += 1024) {
        float4 t = *(const float4*)(xr + i);
        ss += t.x * t.x + t.y * t.y + t.z * t.z + t.w * t.w;
    }
    #pragma unroll
    for (int o = 16; o > 0; o >>= 1) ss += __shfl_xor_sync(0xffffffffu, ss, o);
    __shared__ float red[8];
    if ((threadIdx.x & 31) == 0) red[threadIdx.x >> 5] = ss;
    __syncthreads();
    float tot = red[0] + red[1] + red[2] + red[3] + red[4] + red[5] + red[6] + red[7];
    float inv = rsqrtf(tot * (1.0f / HIDc) + EPSc);
    fp16* hh = hhi + (size_t)row * HIDc;
    fp16* hl = hlo + (size_t)row * HIDc;
    for (int i = threadIdx.x * 2; i < HIDc; i += 512) {
        float2 t = *(const float2*)(xr + i);
        float2 wv = *(const float2*)(w + i);
        uint32_t hh32, ll32;
        split_pack_h(t.x * inv * wv.x, t.y * inv * wv.y, hh32, ll32);
        *(uint32_t*)(hh + i) = hh32;
        *(uint32_t*)(hl + i) = ll32;
    }
}

// ---------------------------------------------------------------------------
// Weight convert + transpose: W fp32 [K,N] -> Wt fp16 [N,K]
// ---------------------------------------------------------------------------
__global__ void __launch_bounds__(256) convert_w_kernel(
    const float* __restrict__ W, fp16* __restrict__ Wt, int K, int N)
{
    __shared__ float t[32][33];
    int k0 = blockIdx.x * 32;
    int n0 = blockIdx.y * 32;
    int tx = threadIdx.x & 31;
    int ty = threadIdx.x >> 5;
    #pragma unroll
    for (int j = 0; j < 4; j++) {
        int r = ty + 8 * j;
        t[r][tx] = W[(size_t)(k0 + r) * N + n0 + tx];
    }
    __syncthreads();
    #pragma unroll
    for (int j = 0; j < 4; j++) {
        int r = ty + 8 * j;
        Wt[(size_t)(n0 + r) * K + k0 + tx] = __float2half_rn(t[tx][r]);
    }
}

// ---------------------------------------------------------------------------
// fp16 2-term GEMM, 128(M)x64(N), BK=64, 2-stage, 2 CTAs/SM.
// Fused epilogue modes:
//   0: C = acc (+res); 1: C = rope(acc+bias) fp32;
//   2: rope(acc+bias) -> cache fp32 + single fp16 (shf);
//   3: (acc+bias)     -> cache fp32 + single fp16 (shf).
// ---------------------------------------------------------------------------
#define GA_BYTES 16384
#define GB_BYTES 8192
#define G_STAGE  40960
#define GM_SMEM_TOTAL (2 * G_STAGE)   // 81920

__global__ void __launch_bounds__(256, 2) gemm_fp16_kernel(
    const fp16* __restrict__ Ahi, const fp16* __restrict__ Alo,
    const fp16* __restrict__ B,
    const float* __restrict__ bias, const float* __restrict__ res,
    float* __restrict__ C, int N, int K,
    int mode,
    const float* __restrict__ cosb, const float* __restrict__ sinb,
    const int* __restrict__ pos,
    float* __restrict__ cacheOut, fp16* __restrict__ shf)
{
    extern __shared__ char smem[];
    uint32_t sb = smem_to_u32(smem);
    int tid  = threadIdx.x;
    int wid  = tid >> 5;
    int lane = tid & 31;
    int rowBase = blockIdx.y * 128;
    int colBase = blockIdx.x * 64;

    int wm = wid & 3;
    int wn = wid >> 2;
    int wmBase = wm * 32;
    int wnBase = wn * 32;

    const fp16* gA0 = Ahi + (size_t)rowBase * K;
    const fp16* gA1 = Alo + (size_t)rowBase * K;
    const fp16* gB  = B  + (size_t)colBase * K;

    float acc[2][4][4];
    #pragma unroll
    for (int i = 0; i < 2; i++)
        #pragma unroll
        for (int j = 0; j < 4; j++)
            #pragma unroll
            for (int c = 0; c < 4; c++) acc[i][j][c] = 0.f;

    const int KT = K >> 6;

    auto load_stage = [&](int kt, int buf) {
        uint32_t base = sb + buf * G_STAGE;
        int kOff = kt * 64;
        #pragma unroll
        for (int i = 0; i < 4; i++) {
            int c = tid + i * 256;
            size_t g = (size_t)(c >> 3) * K + kOff + (c & 7) * 8;
            uint32_t so = SMEM_SWIZZLE_128B((uint32_t)((c >> 3) * 128 + (c & 7) * 16));
            cp_async16(base + so, gA0 + g);
            cp_async16(base + GA_BYTES + so, gA1 + g);
        }
        #pragma unroll
        for (int i = 0; i < 2; i++) {
            int c = tid + i * 256;
            size_t g = (size_t)(c >> 3) * K + kOff + (c & 7) * 8;
            uint32_t so = SMEM_SWIZZLE_128B((uint32_t)((c >> 3) * 128 + (c & 7) * 16));
            cp_async16(base + 2 * GA_BYTES + so, gB + g);
        }
    };

    load_stage(0, 0);
    CP_COMMIT();

    int aRow = wmBase + (lane & 15);
    int aKs  = (lane >> 4) << 4;
    int bRow = wnBase + ((lane >> 4) << 3) + (lane & 7);
    int bKs  = ((lane >> 3) & 1) << 4;

    for (int kt = 0; kt < KT; kt++) {
        int buf = kt & 1;
        if (kt + 1 < KT) {
            load_stage(kt + 1, buf ^ 1);
            CP_COMMIT();
            CP_WAIT1();
        } else {
            CP_WAIT0();
        }
        __syncthreads();

        uint32_t mb = sb + buf * G_STAGE;
        uint32_t mbA0 = mb;
        uint32_t mbA1 = mb + GA_BYTES;
        uint32_t mbB  = mb + 2 * GA_BYTES;
        #pragma unroll
        for (int ks = 0; ks < 4; ks++) {
            int kb = ks * 32;
            uint32_t aA[2][4], aC[2][4], bB[4][2];
            #pragma unroll
            for (int i = 0; i < 2; i++)
                ldsm4(aA[i][0], aA[i][1], aA[i][2], aA[i][3],
                      mbA0 + SMEM_SWIZZLE_128B((aRow + i * 16) * 128 + kb + aKs));
            #pragma unroll
            for (int j = 0; j < 2; j++)
                ldsm4(bB[2 * j][0], bB[2 * j][1], bB[2 * j + 1][0], bB[2 * j + 1][1],
                      mbB + SMEM_SWIZZLE_128B((bRow + j * 16) * 128 + kb + bKs));
            #pragma unroll
            for (int i = 0; i < 2; i++)
                #pragma unroll
                for (int j = 0; j < 4; j++) mma16816h(acc[i][j], aA[i], bB[j]);
            #pragma unroll
            for (int i = 0; i < 2; i++)
                ldsm4(aC[i][0], aC[i][1], aC[i][2], aC[i][3],
                      mbA1 + SMEM_SWIZZLE_128B((aRow + i * 16) * 128 + kb + aKs));
            #pragma unroll
            for (int i = 0; i < 2; i++)
                #pragma unroll
                for (int j = 0; j < 4; j++) mma16816h(acc[i][j], aC[i], bB[j]);
        }
        __syncthreads();
    }

    // ---- fused epilogue ----
    #pragma unroll
    for (int i = 0; i < 2; i++) {
        #pragma unroll
        for (int j = 0; j < 4; j++) {
            int col = colBase + wnBase + j * 8 + (lane & 3) * 2;   // even
            int r0 = rowBase + wmBase + i * 16 + (lane >> 2);
            int r1 = r0 + 8;
            float b0 = 0.f, b1 = 0.f;
            if (bias) { b0 = __ldg(bias + col); b1 = __ldg(bias + col + 1); }
            float v0 = acc[i][j][0] + b0, v1 = acc[i][j][1] + b1;
            float v2 = acc[i][j][2] + b0, v3 = acc[i][j][3] + b1;
            if (res) {
                const float* p0 = res + (size_t)r0 * N + col;
                const float* p1 = res + (size_t)r1 * N + col;
                v0 += p0[0]; v1 += p0[1];
                v2 += p1[0]; v3 += p1[1];
            }
            if (mode == 1 || mode == 2) {
                int d = col & (Dc - 1);
                float c0 = __ldg(cosb + (size_t)r0 * Dc + d);
                float s0 = __ldg(sinb + (size_t)r0 * Dc + d);
                float c1 = __ldg(cosb + (size_t)r1 * Dc + d);
                float s1 = __ldg(sinb + (size_t)r1 * Dc + d);
                float t0 = v0 * c0 - v1 * s0; v1 = v1 * c0 + v0 * s0; v0 = t0;
                float t2 = v2 * c1 - v3 * s1; v3 = v3 * c1 + v2 * s1; v2 = t2;
            }
            if (mode <= 1) {
                *(float2*)(C + (size_t)r0 * N + col) = make_float2(v0, v1);
                *(float2*)(C + (size_t)r1 * N + col) = make_float2(v2, v3);
            } else {
                int s0i = r0 & (Sc - 1), bb0 = r0 >> 11;
                int s1i = r1 & (Sc - 1), bb1 = r1 >> 11;
                int p0 = __ldg(pos + s0i);
                int p1 = __ldg(pos + s1i);
                *(float2*)(cacheOut + ((size_t)bb0 * MAXSEQ + p0) * N + col) = make_float2(v0, v1);
                *(float2*)(cacheOut + ((size_t)bb1 * MAXSEQ + p1) * N + col) = make_float2(v2, v3);
                __half2 h0 = __floats2half2_rn(v0, v1);
                __half2 h1 = __floats2half2_rn(v2, v3);
                *(uint32_t*)(shf + (size_t)r0 * N + col) = *(uint32_t*)&h0;
                *(uint32_t*)(shf + (size_t)r1 * N + col) = *(uint32_t*)&h1;
            }
        }
    }
}

// ---------------------------------------------------------------------------
// Tensor-core flash attention, fp16 2-term:
//   S = (Qhi + Qlo) · K   (K single fp16)
//   O += (Phi + Plo) · V  (V single fp16)
// Stage = K(16KB) + V(16KB) = 32KB; 3 stages = 96KB.
// ---------------------------------------------------------------------------
#define FT_STAGE 32768
#define FT_SMEM (3 * FT_STAGE)   // 98304

__global__ void __launch_bounds__(256, 1) flash_mma_kernel(
    const float* __restrict__ q,
    const fp16* __restrict__ khf, const fp16* __restrict__ vhf,
    fp16* __restrict__ ohi, fp16* __restrict__ olo)
{
    extern __shared__ char smem[];
    uint32_t sb = smem_to_u32(smem);
    int qt = gridDim.x - 1 - blockIdx.x;
    int h = blockIdx.y, b = blockIdx.z;
    int kvh = h >> 2;
    int tid = threadIdx.x, wid = tid >> 5, lane = tid & 31;
    int qbase = qt * 128;
    int r0 = qbase + wid * 16 + (lane >> 2);

    const float scale = 0.08838834764831845f * 1.4426950408889634f;

    uint32_t qa_hi[8][4], qa_lo[8][4];
    {
        const float* q0 = q + (((size_t)b * Sc + r0) * Hc + h) * Dc;
        const float* q1 = q0 + (size_t)8 * Hc * Dc;
        #pragma unroll
        for (int kk = 0; kk < 8; kk++) {
            int c0 = kk * 16 + (lane & 3) * 2;
            split_pack_h(q0[c0] * scale, q0[c0 + 1] * scale, qa_hi[kk][0], qa_lo[kk][0]);
            split_pack_h(q1[c0] * scale, q1[c0 + 1] * scale, qa_hi[kk][1], qa_lo[kk][1]);
            split_pack_h(q0[c0 + 8] * scale, q0[c0 + 9] * scale, qa_hi[kk][2], qa_lo[kk][2]);
            split_pack_h(q1[c0 + 8] * scale, q1[c0 + 9] * scale, qa_hi[kk][3], qa_lo[kk][3]);
        }
    }

    float oacc[16][4];
    #pragma unroll
    for (int j = 0; j < 16; j++)
        #pragma unroll
        for (int c = 0; c < 4; c++) oacc[j][c] = 0.f;
    float m0 = NEG_INF, m1 = NEG_INF, l0 = 0.f, l1 = 0.f;

    const fp16* mats[2];
    {
        size_t off = (size_t)b * Sc * KVc * Dc + (size_t)kvh * Dc;
        mats[0] = khf + off; mats[1] = vhf + off;
    }

    const int NT = 2 * qt + 2;

    auto load_stage = [&](int kt, int buf) {
        int kb = kt * 64;
        #pragma unroll
        for (int i = 0; i < 8; i++) {
            int idx = tid + i * 256;
            int mm = idx >> 10;           // 0..1
            int t  = (idx >> 4) & 63;
            int c  = idx & 15;
            const fp16* src = mats[mm] + (size_t)(kb + t) * (KVc * Dc) + c * 8;
            uint32_t dst = sb + buf * FT_STAGE + mm * 16384 + (c >> 3) * 8192
                         + SMEM_SWIZZLE_128B(t * 128 + (c & 7) * 16);
            cp_async16(dst, src);
        }
    };

    load_stage(0, 0);
    CP_COMMIT();
    if (NT > 1) { load_stage(1, 1); CP_COMMIT(); }

    int g = lane >> 3;
    int keyl_k = (g >> 1) * 8 + (lane & 7);
    int d16_k  = (g & 1) * 16;
    int keyl_v = (g & 1) * 8 + (lane & 7);
    int dv8    = (g >> 1) * 8;

    for (int kt = 0; kt < NT; kt++) {
        int buf = kt % 3;
        if (kt + 2 < NT) {
            load_stage(kt + 2, (kt + 2) % 3);
            CP_COMMIT();
            CP_WAIT2();
        } else if (kt + 1 < NT) {
            CP_WAIT1();
        } else {
            CP_WAIT0();
        }
        __syncthreads();

        int kb = kt * 64;
        bool active = kb <= qbase + wid * 16 + 15;
        if (active) {
            uint32_t Kt = sb + buf * FT_STAGE;
            uint32_t Vt = Kt + 16384;

            float sacc[8][4];
            #pragma unroll
            for (int j = 0; j < 8; j++)
                #pragma unroll
                for (int c = 0; c < 4; c++) sacc[j][c] = 0.f;

            // ---- S = (Qhi + Qlo) K ----
            #pragma unroll
            for (int ks = 0; ks < 8; ks++) {
                uint32_t sub = (ks >> 2) * 8192;
                int db = (ks & 3) * 32 + d16_k;
                uint32_t bh[8][2];
                #pragma unroll
                for (int g4 = 0; g4 < 4; g4++) {
                    uint32_t a = SMEM_SWIZZLE_128B((g4 * 16 + keyl_k) * 128 + db);
                    ldsm4(bh[2 * g4][0], bh[2 * g4][1], bh[2 * g4 + 1][0], bh[2 * g4 + 1][1],
                          Kt + sub + a);
                }
                #pragma unroll
                for (int j = 0; j < 8; j++) mma16816h(sacc[j], qa_hi[ks], bh[j]);
                #pragma unroll
                for (int j = 0; j < 8; j++) mma16816h(sacc[j], qa_lo[ks], bh[j]);
            }

            if (kb + 64 > qbase + wid * 16) {
                #pragma unroll
                for (int j = 0; j < 8; j++) {
                    int col = kb + j * 8 + (lane & 3) * 2;
                    if (col > r0)     sacc[j][0] = NEG_INF;
                    if (col + 1 > r0) sacc[j][1] = NEG_INF;
                    if (col > r0 + 8)     sacc[j][2] = NEG_INF;
                    if (col + 1 > r0 + 8) sacc[j][3] = NEG_INF;
                }
            }

            float tm0 = NEG_INF, tm1 = NEG_INF;
            #pragma unroll
            for (int j = 0; j < 8; j++) {
                tm0 = fmaxf(tm0, fmaxf(sacc[j][0], sacc[j][1]));
                tm1 = fmaxf(tm1, fmaxf(sacc[j][2], sacc[j][3]));
            }
            tm0 = fmaxf(tm0, __shfl_xor_sync(0xffffffffu, tm0, 1));
            tm0 = fmaxf(tm0, __shfl_xor_sync(0xffffffffu, tm0, 2));
            tm1 = fmaxf(tm1, __shfl_xor_sync(0xffffffffu, tm1, 1));
            tm1 = fmaxf(tm1, __shfl_xor_sync(0xffffffffu, tm1, 2));
            float mn0 = fmaxf(m0, tm0), mn1 = fmaxf(m1, tm1);
            float cor0 = ex2(m0 - mn0), cor1 = ex2(m1 - mn1);
            l0 *= cor0; l1 *= cor1;
            if (m0 != mn0 || m1 != mn1) {
                #pragma unroll
                for (int j = 0; j < 16; j++) {
                    oacc[j][0] *= cor0; oacc[j][1] *= cor0;
                    oacc[j][2] *= cor1; oacc[j][3] *= cor1;
                }
            }
            m0 = mn0; m1 = mn1;

            uint32_t pa_hi[4][4], pa_lo[4][4];
            float ps0 = 0.f, ps1 = 0.f;
            #pragma unroll
            for (int half = 0; half < 2; half++) {
                #pragma unroll
                for (int j = 4 * half; j < 4 * half + 4; j++) {
                    float p0 = ex2(sacc[j][0] - mn0);
                    float p1 = ex2(sacc[j][1] - mn0);
                    float p2 = ex2(sacc[j][2] - mn1);
                    float p3 = ex2(sacc[j][3] - mn1);
                    ps0 += p0 + p1; ps1 += p2 + p3;
                    int kk = j >> 1;
                    int base = (j & 1) ? 2 : 0;
                    split_pack_h(p0, p1, pa_hi[kk][base + 0], pa_lo[kk][base + 0]);
                    split_pack_h(p2, p3, pa_hi[kk][base + 1], pa_lo[kk][base + 1]);
                }
                // ---- O += (Phi + Plo) V ----
                #pragma unroll
                for (int kk = 2 * half; kk < 2 * half + 2; kk++) {
                    #pragma unroll
                    for (int j = 0; j < 8; j++) {
                        int dd = j * 16 + dv8;
                        uint32_t sub = (dd >> 6) * 8192;
                        uint32_t a = SMEM_SWIZZLE_128B((kk * 16 + keyl_v) * 128 + (dd & 63) * 2);
                        uint32_t vb[2][2];
                        ldsm4t(vb[0][0], vb[0][1], vb[1][0], vb[1][1], Vt + sub + a);
                        mma16816h(oacc[2 * j],     pa_hi[kk], vb[0]);
                        mma16816h(oacc[2 * j + 1], pa_hi[kk], vb[1]);
                        mma16816h(oacc[2 * j],     pa_lo[kk], vb[0]);
                        mma16816h(oacc[2 * j + 1], pa_lo[kk], vb[1]);
                    }
                }
            }
            l0 += ps0; l1 += ps1;
        }
        __syncthreads();
    }

    l0 += __shfl_xor_sync(0xffffffffu, l0, 1);
    l0 += __shfl_xor_sync(0xffffffffu, l0, 2);
    l1 += __shfl_xor_sync(0xffffffffu, l1, 1);
    l1 += __shfl_xor_sync(0xffffffffu, l1, 2);
    float inv0 = 1.0f / l0, inv1 = 1.0f / l1;

    size_t ob0 = (((size_t)b * Sc + r0) * Hc + h) * Dc;
    size_t ob1 = ob0 + (size_t)8 * Hc * Dc;
    #pragma unroll
    for (int j = 0; j < 16; j++) {
        int col = j * 8 + (lane & 3) * 2;
        uint32_t hh, ll;
        split_pack_h(oacc[j][0] * inv0, oacc[j][1] * inv0, hh, ll);
        *(uint32_t*)(ohi + ob0 + col) = hh;
        *(uint32_t*)(olo + ob0 + col) = ll;
        split_pack_h(oacc[j][2] * inv1, oacc[j][3] * inv1, hh, ll);
        *(uint32_t*)(ohi + ob1 + col) = hh;
        *(uint32_t*)(olo + ob1 + col) = ll;
    }
}

// ---------------------------------------------------------------------------
// Launch (single stream, fused-epilogue structure)
// ---------------------------------------------------------------------------
extern "C" void kernel_launch(void* const* d_in, const int* in_sizes, int n_in,
                              void* d_out, int out_size)
{
    const float* hidden = (const float*)d_in[0];
    const float* lnw    = (const float*)d_in[1];
    const float* Wq     = (const float*)d_in[2];
    const float* bq     = (const float*)d_in[3];
    const float* Wk     = (const float*)d_in[4];
    const float* bk     = (const float*)d_in[5];
    const float* Wv     = (const float*)d_in[6];
    const float* bv     = (const float*)d_in[7];
    const float* Wo     = (const float*)d_in[8];
    const float* cosb   = (const float*)d_in[9];
    const float* sinb   = (const float*)d_in[10];
    const float* kc_in  = (const float*)d_in[11];
    const float* vc_in  = (const float*)d_in[12];
    const int*   pos    = (const int*)d_in[13];

    float* out = (float*)d_out;
    const size_t OUTE = (size_t)Bc * Sc * HIDc;
    const size_t CE   = (size_t)Bc * MAXSEQ * KVc * Dc;
    float* kc_out = out + OUTE;
    float* vc_out = kc_out + CE;

    fp16 *hhi, *hlo, *wqt, *wkt, *wvt, *wot, *ctx_hi, *ctx_lo, *khf, *vhf;
    float *q_p;
    cudaGetSymbolAddress((void**)&hhi, g_hhi);
    cudaGetSymbolAddress((void**)&hlo, g_hlo);
    cudaGetSymbolAddress((void**)&wqt, g_wqt);
    cudaGetSymbolAddress((void**)&wkt, g_wkt);
    cudaGetSymbolAddress((void**)&wvt, g_wvt);
    cudaGetSymbolAddress((void**)&wot, g_wot);
    cudaGetSymbolAddress((void**)&ctx_hi, g_ctx_hi);
    cudaGetSymbolAddress((void**)&ctx_lo, g_ctx_lo);
    cudaGetSymbolAddress((void**)&khf, g_khf);
    cudaGetSymbolAddress((void**)&vhf, g_vhf);
    cudaGetSymbolAddress((void**)&q_p, g_q);

    cudaFuncSetAttribute(gemm_fp16_kernel, cudaFuncAttributeMaxDynamicSharedMemorySize, GM_SMEM_TOTAL);
    cudaFuncSetAttribute(flash_mma_kernel, cudaFuncAttributeMaxDynamicSharedMemorySize, FT_SMEM);

    const int M = Bc * Sc;

    // 0: rmsnorm (fp16 hi/lo out)
    rmsnorm_split_kernel<<<M, 256>>>(hidden, lnw, hhi, hlo);
    // 1: convert Wq
    convert_w_kernel<<<dim3(HIDc / 32, (Hc * Dc) / 32), 256>>>(Wq, wqt, HIDc, Hc * Dc);
    // 2: Q projection + fused RoPE
    gemm_fp16_kernel<<<dim3((Hc * Dc) / 64, M / 128), 256, GM_SMEM_TOTAL>>>(
        hhi, hlo, wqt, bq, nullptr, q_p, Hc * Dc, HIDc,
        1, cosb, sinb, nullptr, nullptr, nullptr);
    // 3: convert Wk
    convert_w_kernel<<<dim3(HIDc / 32, (KVc * Dc) / 32), 256>>>(Wk, wkt, HIDc, KVc * Dc);
    // 4: K projection + fused RoPE + cache + fp16
    gemm_fp16_kernel<<<dim3((KVc * Dc) / 64, M / 128), 256, GM_SMEM_TOTAL>>>(
        hhi, hlo, wkt, bk, nullptr, nullptr, KVc * Dc, HIDc,
        2, cosb, sinb, pos, kc_out, khf);
    // 5: convert Wv
    convert_w_kernel<<<dim3(HIDc / 32, (KVc * Dc) / 32), 256>>>(Wv, wvt, HIDc, KVc * Dc);
    // 6: V projection + cache + fp16
    gemm_fp16_kernel<<<dim3((KVc * Dc) / 64, M / 128), 256, GM_SMEM_TOTAL>>>(
        hhi, hlo, wvt, bv, nullptr, nullptr, KVc * Dc, HIDc,
        3, nullptr, nullptr, pos, vc_out, vhf);
    // 7: convert Wo
    convert_w_kernel<<<dim3((Hc * Dc) / 32, HIDc / 32), 256>>>(Wo, wot, Hc * Dc, HIDc);
    // 8: flash attention (fp16 2-term, fp16 ctx hi/lo out)
    flash_mma_kernel<<<dim3(Sc / 128, Hc, Bc), 256, FT_SMEM>>>(
        q_p, khf, vhf, ctx_hi, ctx_lo);
    // 9: O projection + residual
    gemm_fp16_kernel<<<dim3(HIDc / 64, M / 128), 256, GM_SMEM_TOTAL>>>(
        ctx_hi, ctx_lo, wot, nullptr, hidden, out, HIDc, HIDc,
        0, nullptr, nullptr, nullptr, nullptr, nullptr);
    // cache tail copies (rows [S, MAX_SEQ) only)
    const size_t ROWS = (size_t)KVc * Dc;
    const size_t TAIL = (size_t)(MAXSEQ - Sc) * ROWS;
    for (int b = 0; b < Bc; b++) {
        size_t off = ((size_t)b * MAXSEQ + Sc) * ROWS;
        cudaMemcpyAsync(kc_out + off, kc_in + off, TAIL * sizeof(float), cudaMemcpyDeviceToDevice);
        cudaMemcpyAsync(vc_out + off, vc_in + off, TAIL * sizeof(float), cudaMemcpyDeviceToDevice);
    }
}